// round 2
// baseline (speedup 1.0000x reference)
#include <cuda_runtime.h>
#include <cstdint>

#define NN 50000
#define NE 800000
#define NG 64
#define EPSV 1e-5f

// ---------------- scratch (device globals; no allocations allowed) ----------------
__device__ float g_bufA[NN * 256];
__device__ float g_bufB[NN * 256];
__device__ float g_dinv[NN];
__device__ int   g_deg[NN];
__device__ int   g_rowstart[NN + 1];
__device__ int   g_fill[NN];
__device__ int   g_csr[NE];
__device__ float g_bnsum[192];
__device__ float g_bnsq[192];
__device__ float g_a[192];   // [0:128) bn1 scale, [128:192) bn2 scale
__device__ float g_c[192];   // matching shifts
__device__ float g_pool[NG * 64];
__device__ int   g_cnt[NG];

// ---------------- setup kernels ----------------
__global__ void zero_kernel() {
    int i = blockIdx.x * 256 + threadIdx.x;
    if (i < NN) g_deg[i] = 0;
    if (i < 192) { g_bnsum[i] = 0.f; g_bnsq[i] = 0.f; }
}

__global__ void count_kernel(const int* __restrict__ dst) {
    int e = blockIdx.x * 256 + threadIdx.x;
    if (e < NE) atomicAdd(&g_deg[dst[e]], 1);
}

// Single-block exclusive scan over degrees; also computes deg^-1/2 (with self-loop)
// and resets fill cursors.
__global__ void scan_kernel() {
    const int T = 1024;
    int tid = threadIdx.x;
    int chunk = (NN + T - 1) / T;
    int lo = tid * chunk;
    int hi = lo + chunk; if (hi > NN) hi = NN;
    int s = 0;
    for (int i = lo; i < hi; i++) s += g_deg[i];

    __shared__ int warpsum[32];
    int lane = tid & 31, wid = tid >> 5;
    int incl = s;
    #pragma unroll
    for (int o = 1; o < 32; o <<= 1) {
        int v = __shfl_up_sync(0xffffffffu, incl, o);
        if (lane >= o) incl += v;
    }
    if (lane == 31) warpsum[wid] = incl;
    __syncthreads();
    if (wid == 0) {
        int w = warpsum[lane];
        int wincl = w;
        #pragma unroll
        for (int o = 1; o < 32; o <<= 1) {
            int v = __shfl_up_sync(0xffffffffu, wincl, o);
            if (lane >= o) wincl += v;
        }
        warpsum[lane] = wincl - w;  // exclusive
    }
    __syncthreads();
    int run = (incl - s) + warpsum[wid];
    for (int i = lo; i < hi; i++) {
        g_rowstart[i] = run;
        int d = g_deg[i];
        run += d;
        g_dinv[i] = rsqrtf((float)(d + 1));  // +1: self-loop
        g_fill[i] = 0;
    }
    if (tid == T - 1) g_rowstart[NN] = run;
}

__global__ void fill_kernel(const int* __restrict__ src, const int* __restrict__ dst) {
    int e = blockIdx.x * 256 + threadIdx.x;
    if (e < NE) {
        int d = dst[e];
        int pos = g_rowstart[d] + atomicAdd(&g_fill[d], 1);
        g_csr[pos] = src[e];
    }
}

// ---------------- layer 1 GEMM (K=5) fused with dinv pre-scale ----------------
__global__ void layer1_kernel(const float* __restrict__ x, const float* __restrict__ W1,
                              float* __restrict__ u) {
    __shared__ float w[5 * 256];
    for (int i = threadIdx.x; i < 1280; i += 256) w[i] = W1[i];
    __syncthreads();
    int idx = blockIdx.x * 256 + threadIdx.x;   // node*64 + chunk
    if (idx >= NN * 64) return;
    int node = idx >> 6;
    int c = (idx & 63) * 4;
    float xs[5];
    #pragma unroll
    for (int k = 0; k < 5; k++) xs[k] = x[node * 5 + k];
    float4 acc = make_float4(0.f, 0.f, 0.f, 0.f);
    #pragma unroll
    for (int k = 0; k < 5; k++) {
        float xv = xs[k];
        acc.x = fmaf(xv, w[k * 256 + c + 0], acc.x);
        acc.y = fmaf(xv, w[k * 256 + c + 1], acc.y);
        acc.z = fmaf(xv, w[k * 256 + c + 2], acc.z);
        acc.w = fmaf(xv, w[k * 256 + c + 3], acc.w);
    }
    float d = g_dinv[node];
    acc.x *= d; acc.y *= d; acc.z *= d; acc.w *= d;
    ((float4*)u)[idx] = acc;
}

// ---------------- tiled SGEMM with optional per-k affine(A) and dinv row-scale ----------------
template <int BM, int BN, int BK, int TM, int TN>
__global__ void gemm_kernel(const float* __restrict__ A, const float* __restrict__ W,
                            float* __restrict__ out, int M, int K, int N,
                            const float* __restrict__ affA, const float* __restrict__ affC,
                            const float* __restrict__ rowscale) {
    __shared__ float As[BK][BM + 4];
    __shared__ float Bs[BK][BN];
    const int THREADS = (BM / TM) * (BN / TN);
    int tid = threadIdx.x;
    int tm = tid / (BN / TN);
    int tn = tid % (BN / TN);
    int rowBase = blockIdx.y * BM;
    int colBase = blockIdx.x * BN;
    float acc[TM][TN];
    #pragma unroll
    for (int i = 0; i < TM; i++)
        #pragma unroll
        for (int j = 0; j < TN; j++) acc[i][j] = 0.f;

    for (int k0 = 0; k0 < K; k0 += BK) {
        for (int i = tid; i < BM * BK; i += THREADS) {
            int m = i / BK, k = i % BK;
            int gr = rowBase + m;
            float v = (gr < M) ? A[gr * K + k0 + k] : 0.f;
            if (affA) v = fmaf(v, affA[k0 + k], affC[k0 + k]);
            As[k][m] = v;
        }
        for (int i = tid; i < BK * BN; i += THREADS) {
            int k = i / BN, n = i % BN;
            Bs[k][n] = W[(k0 + k) * N + colBase + n];
        }
        __syncthreads();
        #pragma unroll
        for (int k = 0; k < BK; k++) {
            float a[TM], b[TN];
            #pragma unroll
            for (int i = 0; i < TM; i++) a[i] = As[k][tm * TM + i];
            #pragma unroll
            for (int j = 0; j < TN; j++) b[j] = Bs[k][tn * TN + j];
            #pragma unroll
            for (int i = 0; i < TM; i++)
                #pragma unroll
                for (int j = 0; j < TN; j++) acc[i][j] = fmaf(a[i], b[j], acc[i][j]);
        }
        __syncthreads();
    }
    #pragma unroll
    for (int i = 0; i < TM; i++) {
        int gr = rowBase + tm * TM + i;
        if (gr < M) {
            float rs = rowscale ? rowscale[gr] : 1.f;
            #pragma unroll
            for (int j = 0; j < TN; j++)
                out[gr * N + colBase + tn * TN + j] = acc[i][j] * rs;
        }
    }
}

// ---------------- CSR aggregation: out[i] = relu(dinv[i]*(u[i] + sum_src u[src]) + b) ----------------
template <int F>
__global__ void agg_kernel(const float* __restrict__ u, const float* __restrict__ bias,
                           float* __restrict__ out) {
    constexpr int CH = F / 4;          // float4 lanes per node
    constexpr int NPB = 256 / CH;      // nodes per block
    int node = blockIdx.x * NPB + threadIdx.x / CH;
    int lane = threadIdx.x % CH;
    if (node >= NN) return;
    const float4* u4 = (const float4*)u;
    float4 acc = u4[node * CH + lane];   // self-loop term
    int s = g_rowstart[node];
    int e = g_rowstart[node + 1];
    for (int j = s; j < e; j++) {
        int src = g_csr[j];
        float4 v = __ldg(&u4[src * CH + lane]);
        acc.x += v.x; acc.y += v.y; acc.z += v.z; acc.w += v.w;
    }
    float d = g_dinv[node];
    float4 b = ((const float4*)bias)[lane];
    float4 o;
    o.x = fmaxf(fmaf(d, acc.x, b.x), 0.f);
    o.y = fmaxf(fmaf(d, acc.y, b.y), 0.f);
    o.z = fmaxf(fmaf(d, acc.z, b.z), 0.f);
    o.w = fmaxf(fmaf(d, acc.w, b.w), 0.f);
    ((float4*)out)[node * CH + lane] = o;
}

// ---------------- batchnorm stats (sum / sumsq per feature) ----------------
__global__ void bn_stats(const float* __restrict__ h, int F,
                         float* __restrict__ sums, float* __restrict__ sqs) {
    __shared__ float ss[256], sq[256];
    int tid = threadIdx.x;
    long long idx = (long long)blockIdx.x * 256 + tid;
    long long total = (long long)NN * F;
    long long stride = (long long)gridDim.x * 256;   // multiple of F (F in {64,128})
    float s = 0.f, q = 0.f;
    for (; idx < total; idx += stride) {
        float v = h[idx];
        s += v; q += v * v;
    }
    ss[tid] = s; sq[tid] = q;
    __syncthreads();
    for (int off = 128; off >= F; off >>= 1) {
        if (tid < off) { ss[tid] += ss[tid + off]; sq[tid] += sq[tid + off]; }
        __syncthreads();
    }
    if (tid < F) {
        atomicAdd(&sums[tid], ss[tid]);
        atomicAdd(&sqs[tid], sq[tid]);
    }
}

__global__ void bn_finalize(const float* __restrict__ sums, const float* __restrict__ sqs,
                            const float* __restrict__ gamma, const float* __restrict__ beta,
                            float* __restrict__ a, float* __restrict__ c, int F) {
    int f = threadIdx.x;
    if (f < F) {
        float mean = sums[f] * (1.0f / NN);
        float var = sqs[f] * (1.0f / NN) - mean * mean;
        float aa = gamma[f] * rsqrtf(var + EPSV);
        a[f] = aa;
        c[f] = beta[f] - mean * aa;
    }
}

// ---------------- global mean pool (batch is sorted -> binary search per graph) ----------------
__device__ __forceinline__ int lower_bound_i(const int* arr, int n, int val) {
    int lo = 0, hi = n;
    while (lo < hi) {
        int mid = (lo + hi) >> 1;
        if (arr[mid] < val) lo = mid + 1; else hi = mid;
    }
    return lo;
}

__global__ void pool_kernel(const int* __restrict__ batch, const float* __restrict__ h) {
    int g = blockIdx.x;
    int start = lower_bound_i(batch, NN, g);
    int end   = lower_bound_i(batch, NN, g + 1);
    int tid = threadIdx.x;
    int f = tid & 63, r0 = tid >> 6;
    float s = 0.f;
    for (int r = start + r0; r < end; r += 4) s += h[r * 64 + f];
    __shared__ float sm[256];
    sm[tid] = s;
    __syncthreads();
    if (tid < 128) sm[tid] += sm[tid + 128];
    __syncthreads();
    if (tid < 64) g_pool[g * 64 + tid] = sm[tid] + sm[tid + 64];
    if (tid == 0) g_cnt[g] = end - start;
}

// ---------------- final: bn2 (affine, folded) + mean + FC ----------------
__global__ void final_kernel(const float* __restrict__ Wfc, const float* __restrict__ bfc,
                             float* __restrict__ out) {
    int t = threadIdx.x;
    if (t >= NG * 6) return;
    int g = t / 6, cl = t % 6;
    float cnt = (float)g_cnt[g];
    float inv = 1.f / fmaxf(cnt, 1.f);
    float acc = bfc[cl];
    #pragma unroll
    for (int j = 0; j < 64; j++) {
        float p = fmaf(g_a[128 + j], g_pool[g * 64 + j] * inv, g_c[128 + j]);
        acc = fmaf(p, Wfc[j * 6 + cl], acc);
    }
    out[g * 6 + cl] = acc;
}

// ---------------- host orchestration ----------------
extern "C" void kernel_launch(void* const* d_in, const int* in_sizes, int n_in,
                              void* d_out, int out_size) {
    const float* x      = (const float*)d_in[0];
    const int*   edge   = (const int*)d_in[1];   // int32 (JAX x64 disabled)
    const int*   batch  = (const int*)d_in[2];   // int32
    const float* W1     = (const float*)d_in[3];
    const float* b1     = (const float*)d_in[4];
    const float* W2     = (const float*)d_in[5];
    const float* b2     = (const float*)d_in[6];
    const float* gamma1 = (const float*)d_in[7];
    const float* beta1  = (const float*)d_in[8];
    const float* W3     = (const float*)d_in[9];
    const float* b3     = (const float*)d_in[10];
    const float* gamma2 = (const float*)d_in[11];
    const float* beta2  = (const float*)d_in[12];
    const float* Wfc    = (const float*)d_in[13];
    const float* bfc    = (const float*)d_in[14];
    float* out = (float*)d_out;

    const int* srcp = edge;
    const int* dstp = edge + NE;

    float *bufA, *bufB, *dinv, *bnsum, *bnsq, *aArr, *cArr;
    cudaGetSymbolAddress((void**)&bufA,  g_bufA);
    cudaGetSymbolAddress((void**)&bufB,  g_bufB);
    cudaGetSymbolAddress((void**)&dinv,  g_dinv);
    cudaGetSymbolAddress((void**)&bnsum, g_bnsum);
    cudaGetSymbolAddress((void**)&bnsq,  g_bnsq);
    cudaGetSymbolAddress((void**)&aArr,  g_a);
    cudaGetSymbolAddress((void**)&cArr,  g_c);

    // graph preprocessing (once per launch, reused by all 3 layers)
    zero_kernel<<<(NN + 255) / 256, 256>>>();
    count_kernel<<<(NE + 255) / 256, 256>>>(dstp);
    scan_kernel<<<1, 1024>>>();
    fill_kernel<<<(NE + 255) / 256, 256>>>(srcp, dstp);

    // layer 1: u = dinv * (x @ W1); agg -> relu -> h1 [N,256]
    layer1_kernel<<<(NN * 64 + 255) / 256, 256>>>(x, W1, bufB);
    agg_kernel<256><<<(NN + 3) / 4, 256>>>(bufB, b1, bufA);

    // layer 2: u = dinv * (h1 @ W2); agg -> relu -> h2 [N,128]; bn1 stats
    gemm_kernel<64, 64, 16, 4, 4><<<dim3(2, (NN + 63) / 64), 256>>>(
        bufA, W2, bufB, NN, 256, 128, nullptr, nullptr, dinv);
    agg_kernel<128><<<(NN + 7) / 8, 256>>>(bufB, b2, bufA);
    bn_stats<<<296, 256>>>(bufA, 128, bnsum, bnsq);
    bn_finalize<<<1, 128>>>(bnsum, bnsq, gamma1, beta1, aArr, cArr, 128);

    // layer 3: bn1 folded into A-load; u = dinv * (bn1(h2) @ W3); agg -> relu -> h3 [N,64]
    gemm_kernel<64, 64, 16, 4, 4><<<dim3(1, (NN + 63) / 64), 256>>>(
        bufA, W3, bufB, NN, 128, 64, aArr, cArr, dinv);
    agg_kernel<64><<<(NN + 15) / 16, 256>>>(bufB, b3, bufA);
    bn_stats<<<296, 256>>>(bufA, 64, bnsum + 128, bnsq + 128);
    bn_finalize<<<1, 64>>>(bnsum + 128, bnsq + 128, gamma2, beta2, aArr + 128, cArr + 128, 64);

    // pool + bn2(folded) + FC
    pool_kernel<<<NG, 256>>>(batch, bufA);
    final_kernel<<<1, 512>>>(Wfc, bfc, out);
}

// round 3
// speedup vs baseline: 1.2832x; 1.2832x over previous
#include <cuda_runtime.h>
#include <cstdint>

#define NN 50000
#define NE 800000
#define NG 64
#define EPSV 1e-5f

// ---------------- scratch (device globals; no allocations allowed) ----------------
__device__ float g_bufA[NN * 256];
__device__ float g_bufB[NN * 256];
__device__ float g_dinv[NN];
__device__ int   g_deg[NN];
__device__ int   g_rowstart[NN + 1];
__device__ int   g_fill[NN];
__device__ int   g_csr[NE];
__device__ float g_bnsum[192];
__device__ float g_bnsq[192];
__device__ float g_a[192];   // [0:128) bn1 scale, [128:192) bn2 scale
__device__ float g_c[192];   // matching shifts
__device__ float g_pool[NG * 64];
__device__ int   g_cnt[NG];

// ---------------- setup kernels ----------------
__global__ void zero_kernel() {
    int i = blockIdx.x * 256 + threadIdx.x;
    if (i < NN) g_deg[i] = 0;
    if (i < 192) { g_bnsum[i] = 0.f; g_bnsq[i] = 0.f; }
}

__global__ void count_kernel(const int* __restrict__ dst) {
    int e = blockIdx.x * 256 + threadIdx.x;
    if (e < NE) atomicAdd(&g_deg[dst[e]], 1);
}

// Single-block exclusive scan over degrees; also computes deg^-1/2 (with self-loop)
// and resets fill cursors.
__global__ void scan_kernel() {
    const int T = 1024;
    int tid = threadIdx.x;
    int chunk = (NN + T - 1) / T;
    int lo = tid * chunk;
    int hi = lo + chunk; if (hi > NN) hi = NN;
    int s = 0;
    for (int i = lo; i < hi; i++) s += g_deg[i];

    __shared__ int warpsum[32];
    int lane = tid & 31, wid = tid >> 5;
    int incl = s;
    #pragma unroll
    for (int o = 1; o < 32; o <<= 1) {
        int v = __shfl_up_sync(0xffffffffu, incl, o);
        if (lane >= o) incl += v;
    }
    if (lane == 31) warpsum[wid] = incl;
    __syncthreads();
    if (wid == 0) {
        int w = warpsum[lane];
        int wincl = w;
        #pragma unroll
        for (int o = 1; o < 32; o <<= 1) {
            int v = __shfl_up_sync(0xffffffffu, wincl, o);
            if (lane >= o) wincl += v;
        }
        warpsum[lane] = wincl - w;  // exclusive
    }
    __syncthreads();
    int run = (incl - s) + warpsum[wid];
    for (int i = lo; i < hi; i++) {
        g_rowstart[i] = run;
        int d = g_deg[i];
        run += d;
        g_dinv[i] = rsqrtf((float)(d + 1));  // +1: self-loop
        g_fill[i] = 0;
    }
    if (tid == T - 1) g_rowstart[NN] = run;
}

__global__ void fill_kernel(const int* __restrict__ src, const int* __restrict__ dst) {
    int e = blockIdx.x * 256 + threadIdx.x;
    if (e < NE) {
        int d = dst[e];
        int pos = g_rowstart[d] + atomicAdd(&g_fill[d], 1);
        g_csr[pos] = src[e];
    }
}

// ---------------- layer-1 input aggregation (width 5; Â(XW) == (ÂX)W) ----------------
// xs[i] = dinv[i] * x[i]
__global__ void prescale_kernel(const float* __restrict__ x, float* __restrict__ xs) {
    int t = blockIdx.x * 256 + threadIdx.x;
    if (t >= NN * 5) return;
    xs[t] = x[t] * g_dinv[t / 5];
}

// xa[i] = dinv[i] * (xs[i] + sum_{src in N(i)} xs[src])
__global__ void agg0_kernel(const float* __restrict__ xs, float* __restrict__ xa) {
    int t = blockIdx.x * 256 + threadIdx.x;
    if (t >= NN * 5) return;
    int node = t / 5, f = t - node * 5;
    float acc = xs[t];
    int s = g_rowstart[node], e = g_rowstart[node + 1];
    for (int j = s; j < e; j++)
        acc += __ldg(&xs[g_csr[j] * 5 + f]);
    xa[t] = g_dinv[node] * acc;
}

// h1 = relu(xa @ W1 + b1), [N,5] -> [N,256]
__global__ void gemm1_kernel(const float* __restrict__ xa, const float* __restrict__ W1,
                             const float* __restrict__ b1, float* __restrict__ h1) {
    __shared__ float w[5 * 256];
    __shared__ float bs[256];
    for (int i = threadIdx.x; i < 1280; i += 256) w[i] = W1[i];
    bs[threadIdx.x] = b1[threadIdx.x];
    __syncthreads();
    int idx = blockIdx.x * 256 + threadIdx.x;   // node*64 + chunk
    if (idx >= NN * 64) return;
    int node = idx >> 6;
    int c = (idx & 63) * 4;
    float xv[5];
    #pragma unroll
    for (int k = 0; k < 5; k++) xv[k] = xa[node * 5 + k];
    float4 acc = make_float4(bs[c], bs[c + 1], bs[c + 2], bs[c + 3]);
    #pragma unroll
    for (int k = 0; k < 5; k++) {
        acc.x = fmaf(xv[k], w[k * 256 + c + 0], acc.x);
        acc.y = fmaf(xv[k], w[k * 256 + c + 1], acc.y);
        acc.z = fmaf(xv[k], w[k * 256 + c + 2], acc.z);
        acc.w = fmaf(xv[k], w[k * 256 + c + 3], acc.w);
    }
    acc.x = fmaxf(acc.x, 0.f); acc.y = fmaxf(acc.y, 0.f);
    acc.z = fmaxf(acc.z, 0.f); acc.w = fmaxf(acc.w, 0.f);
    ((float4*)h1)[idx] = acc;
}

// ---------------- SGEMM v2: 128x{128,64} tiles, 8x8 microtile, float4 loads ----------------
// out[m,n] = rowscale[m] * sum_k affine(A[m,k]) * W[k,n]
template <int BM, int BN, int BK, int TM, int TN>
__global__ void gemm_kernel(const float* __restrict__ A, const float* __restrict__ W,
                            float* __restrict__ out, int M, int K, int N,
                            const float* __restrict__ affA, const float* __restrict__ affC,
                            const float* __restrict__ rowscale) {
    constexpr int THREADS = (BM / TM) * (BN / TN);
    __shared__ float As[BK][BM + 4];
    __shared__ float Bs[BK][BN];
    int tid = threadIdx.x;
    int tn = tid % (BN / TN);
    int tm = tid / (BN / TN);
    int rowBase = blockIdx.y * BM;
    int colBase = blockIdx.x * BN;

    float acc[TM][TN];
    #pragma unroll
    for (int i = 0; i < TM; i++)
        #pragma unroll
        for (int j = 0; j < TN; j++) acc[i][j] = 0.f;

    for (int k0 = 0; k0 < K; k0 += BK) {
        // A tile: BM x BK, vectorized, stored transposed
        #pragma unroll
        for (int t = tid; t < BM * BK / 4; t += THREADS) {
            int m = t / (BK / 4);
            int kq = (t % (BK / 4)) * 4;
            int gr = rowBase + m;
            float4 v = make_float4(0.f, 0.f, 0.f, 0.f);
            if (gr < M) v = *(const float4*)&A[gr * K + k0 + kq];
            if (affA) {
                v.x = fmaf(v.x, affA[k0 + kq + 0], affC[k0 + kq + 0]);
                v.y = fmaf(v.y, affA[k0 + kq + 1], affC[k0 + kq + 1]);
                v.z = fmaf(v.z, affA[k0 + kq + 2], affC[k0 + kq + 2]);
                v.w = fmaf(v.w, affA[k0 + kq + 3], affC[k0 + kq + 3]);
            }
            As[kq + 0][m] = v.x;
            As[kq + 1][m] = v.y;
            As[kq + 2][m] = v.z;
            As[kq + 3][m] = v.w;
        }
        // B tile: BK x BN
        #pragma unroll
        for (int t = tid; t < BK * BN / 4; t += THREADS) {
            int k = t / (BN / 4);
            int nq = (t % (BN / 4)) * 4;
            *(float4*)&Bs[k][nq] = *(const float4*)&W[(k0 + k) * N + colBase + nq];
        }
        __syncthreads();
        #pragma unroll
        for (int k = 0; k < BK; k++) {
            float a[TM], b[TN];
            #pragma unroll
            for (int i = 0; i < TM; i += 4)
                *(float4*)&a[i] = *(const float4*)&As[k][tm * TM + i];
            #pragma unroll
            for (int j = 0; j < TN; j += 4)
                *(float4*)&b[j] = *(const float4*)&Bs[k][tn * TN + j];
            #pragma unroll
            for (int i = 0; i < TM; i++)
                #pragma unroll
                for (int j = 0; j < TN; j++)
                    acc[i][j] = fmaf(a[i], b[j], acc[i][j]);
        }
        __syncthreads();
    }
    #pragma unroll
    for (int i = 0; i < TM; i++) {
        int gr = rowBase + tm * TM + i;
        if (gr < M) {
            float rs = rowscale ? rowscale[gr] : 1.f;
            #pragma unroll
            for (int j = 0; j < TN; j += 4) {
                float4 v = make_float4(acc[i][j] * rs, acc[i][j + 1] * rs,
                                       acc[i][j + 2] * rs, acc[i][j + 3] * rs);
                *(float4*)&out[gr * N + colBase + tn * TN + j] = v;
            }
        }
    }
}

// ---------------- CSR aggregation: out[i] = relu(dinv[i]*(u[i] + sum_src u[src]) + b) ----------------
template <int F>
__global__ void agg_kernel(const float* __restrict__ u, const float* __restrict__ bias,
                           float* __restrict__ out) {
    constexpr int CH = F / 4;          // float4 lanes per node
    constexpr int NPB = 256 / CH;      // nodes per block
    int node = blockIdx.x * NPB + threadIdx.x / CH;
    int lane = threadIdx.x % CH;
    if (node >= NN) return;
    const float4* u4 = (const float4*)u;
    float4 acc = u4[node * CH + lane];   // self-loop term
    int s = g_rowstart[node];
    int e = g_rowstart[node + 1];
    for (int j = s; j < e; j++) {
        int src = g_csr[j];
        float4 v = __ldg(&u4[src * CH + lane]);
        acc.x += v.x; acc.y += v.y; acc.z += v.z; acc.w += v.w;
    }
    float d = g_dinv[node];
    float4 b = ((const float4*)bias)[lane];
    float4 o;
    o.x = fmaxf(fmaf(d, acc.x, b.x), 0.f);
    o.y = fmaxf(fmaf(d, acc.y, b.y), 0.f);
    o.z = fmaxf(fmaf(d, acc.z, b.z), 0.f);
    o.w = fmaxf(fmaf(d, acc.w, b.w), 0.f);
    ((float4*)out)[node * CH + lane] = o;
}

// ---------------- batchnorm stats (sum / sumsq per feature) ----------------
__global__ void bn_stats(const float* __restrict__ h, int F,
                         float* __restrict__ sums, float* __restrict__ sqs) {
    __shared__ float ss[256], sq[256];
    int tid = threadIdx.x;
    long long idx = (long long)blockIdx.x * 256 + tid;
    long long total = (long long)NN * F;
    long long stride = (long long)gridDim.x * 256;   // multiple of F (F in {64,128})
    float s = 0.f, q = 0.f;
    for (; idx < total; idx += stride) {
        float v = h[idx];
        s += v; q += v * v;
    }
    ss[tid] = s; sq[tid] = q;
    __syncthreads();
    for (int off = 128; off >= F; off >>= 1) {
        if (tid < off) { ss[tid] += ss[tid + off]; sq[tid] += sq[tid + off]; }
        __syncthreads();
    }
    if (tid < F) {
        atomicAdd(&sums[tid], ss[tid]);
        atomicAdd(&sqs[tid], sq[tid]);
    }
}

__global__ void bn_finalize(const float* __restrict__ sums, const float* __restrict__ sqs,
                            const float* __restrict__ gamma, const float* __restrict__ beta,
                            float* __restrict__ a, float* __restrict__ c, int F) {
    int f = threadIdx.x;
    if (f < F) {
        float mean = sums[f] * (1.0f / NN);
        float var = sqs[f] * (1.0f / NN) - mean * mean;
        float aa = gamma[f] * rsqrtf(var + EPSV);
        a[f] = aa;
        c[f] = beta[f] - mean * aa;
    }
}

// ---------------- global mean pool (batch is sorted -> binary search per graph) ----------------
__device__ __forceinline__ int lower_bound_i(const int* arr, int n, int val) {
    int lo = 0, hi = n;
    while (lo < hi) {
        int mid = (lo + hi) >> 1;
        if (arr[mid] < val) lo = mid + 1; else hi = mid;
    }
    return lo;
}

__global__ void pool_kernel(const int* __restrict__ batch, const float* __restrict__ h) {
    int g = blockIdx.x;
    int start = lower_bound_i(batch, NN, g);
    int end   = lower_bound_i(batch, NN, g + 1);
    int tid = threadIdx.x;
    int f = tid & 63, r0 = tid >> 6;
    float s = 0.f;
    for (int r = start + r0; r < end; r += 4) s += h[r * 64 + f];
    __shared__ float sm[256];
    sm[tid] = s;
    __syncthreads();
    if (tid < 128) sm[tid] += sm[tid + 128];
    __syncthreads();
    if (tid < 64) g_pool[g * 64 + tid] = sm[tid] + sm[tid + 64];
    if (tid == 0) g_cnt[g] = end - start;
}

// ---------------- final: bn2 (affine, folded) + mean + FC ----------------
__global__ void final_kernel(const float* __restrict__ Wfc, const float* __restrict__ bfc,
                             float* __restrict__ out) {
    int t = threadIdx.x;
    if (t >= NG * 6) return;
    int g = t / 6, cl = t % 6;
    float cnt = (float)g_cnt[g];
    float inv = 1.f / fmaxf(cnt, 1.f);
    float acc = bfc[cl];
    #pragma unroll
    for (int j = 0; j < 64; j++) {
        float p = fmaf(g_a[128 + j], g_pool[g * 64 + j] * inv, g_c[128 + j]);
        acc = fmaf(p, Wfc[j * 6 + cl], acc);
    }
    out[g * 6 + cl] = acc;
}

// ---------------- host orchestration ----------------
extern "C" void kernel_launch(void* const* d_in, const int* in_sizes, int n_in,
                              void* d_out, int out_size) {
    const float* x      = (const float*)d_in[0];
    const int*   edge   = (const int*)d_in[1];   // int32 (JAX x64 disabled)
    const int*   batch  = (const int*)d_in[2];   // int32
    const float* W1     = (const float*)d_in[3];
    const float* b1     = (const float*)d_in[4];
    const float* W2     = (const float*)d_in[5];
    const float* b2     = (const float*)d_in[6];
    const float* gamma1 = (const float*)d_in[7];
    const float* beta1  = (const float*)d_in[8];
    const float* W3     = (const float*)d_in[9];
    const float* b3     = (const float*)d_in[10];
    const float* gamma2 = (const float*)d_in[11];
    const float* beta2  = (const float*)d_in[12];
    const float* Wfc    = (const float*)d_in[13];
    const float* bfc    = (const float*)d_in[14];
    float* out = (float*)d_out;

    const int* srcp = edge;
    const int* dstp = edge + NE;

    float *bufA, *bufB, *dinv, *bnsum, *bnsq, *aArr, *cArr;
    cudaGetSymbolAddress((void**)&bufA,  g_bufA);
    cudaGetSymbolAddress((void**)&bufB,  g_bufB);
    cudaGetSymbolAddress((void**)&dinv,  g_dinv);
    cudaGetSymbolAddress((void**)&bnsum, g_bnsum);
    cudaGetSymbolAddress((void**)&bnsq,  g_bnsq);
    cudaGetSymbolAddress((void**)&aArr,  g_a);
    cudaGetSymbolAddress((void**)&cArr,  g_c);

    // graph preprocessing (once per launch, reused by all 3 layers)
    zero_kernel<<<(NN + 255) / 256, 256>>>();
    count_kernel<<<(NE + 255) / 256, 256>>>(dstp);
    scan_kernel<<<1, 1024>>>();
    fill_kernel<<<(NE + 255) / 256, 256>>>(srcp, dstp);

    // layer 1 (reassociated): xa = Â x (width 5), then h1 = relu(xa @ W1 + b1)
    prescale_kernel<<<(NN * 5 + 255) / 256, 256>>>(x, bufB);          // xs -> bufB
    agg0_kernel<<<(NN * 5 + 255) / 256, 256>>>(bufB, bufA);           // xa -> bufA
    gemm1_kernel<<<(NN * 64 + 255) / 256, 256>>>(bufA, W1, b1, bufB); // h1 -> bufB

    // layer 2: u2 = dinv * (h1 @ W2) -> bufA; agg -> h2 -> bufB; bn1 stats
    gemm_kernel<128, 128, 16, 8, 8><<<dim3(1, (NN + 127) / 128), 256>>>(
        bufB, W2, bufA, NN, 256, 128, nullptr, nullptr, dinv);
    agg_kernel<128><<<(NN + 7) / 8, 256>>>(bufA, b2, bufB);
    bn_stats<<<296, 256>>>(bufB, 128, bnsum, bnsq);
    bn_finalize<<<1, 128>>>(bnsum, bnsq, gamma1, beta1, aArr, cArr, 128);

    // layer 3: bn1 folded into A-load; u3 = dinv * (bn1(h2) @ W3) -> bufA; agg -> h3 -> bufB
    gemm_kernel<128, 64, 16, 8, 8><<<dim3(1, (NN + 127) / 128), 128>>>(
        bufB, W3, bufA, NN, 128, 64, aArr, cArr, dinv);
    agg_kernel<64><<<(NN + 15) / 16, 256>>>(bufA, b3, bufB);
    bn_stats<<<296, 256>>>(bufB, 64, bnsum + 128, bnsq + 128);
    bn_finalize<<<1, 64>>>(bnsum + 128, bnsq + 128, gamma2, beta2, aArr + 128, cArr + 128, 64);

    // pool + bn2(folded) + FC
    pool_kernel<<<NG, 256>>>(batch, bufB);
    final_kernel<<<1, 512>>>(Wfc, bfc, out);
}

// round 4
// speedup vs baseline: 1.3556x; 1.0564x over previous
#include <cuda_runtime.h>
#include <cstdint>

#define NN 50000
#define NE 800000
#define NG 64
#define EPSV 1e-5f

// ---------------- scratch (device globals; no allocations allowed) ----------------
__device__ float g_bufA[NN * 256];
__device__ float g_bufB[NN * 256];
__device__ float g_dinv[NN];
__device__ int   g_deg[NN];
__device__ int   g_rowstart[NN + 1];
__device__ int   g_fill[NN];
__device__ int   g_csr[NE];
__device__ float g_bnsum[192];
__device__ float g_bnsq[192];
__device__ float g_a[192];   // [0:128) bn1 scale, [128:192) bn2 scale
__device__ float g_c[192];   // matching shifts
__device__ float g_pool[NG * 64];
__device__ int   g_cnt[NG];

// ---------------- packed f32x2 helpers (Blackwell FFMA2 path) ----------------
__device__ __forceinline__ unsigned long long pack2(float lo, float hi) {
    unsigned long long r;
    asm("mov.b64 %0, {%1, %2};" : "=l"(r) : "f"(lo), "f"(hi));
    return r;
}
__device__ __forceinline__ void unpack2(unsigned long long v, float& lo, float& hi) {
    asm("mov.b64 {%0, %1}, %2;" : "=f"(lo), "=f"(hi) : "l"(v));
}
__device__ __forceinline__ unsigned long long fma2(unsigned long long a,
                                                   unsigned long long b,
                                                   unsigned long long c) {
    unsigned long long d;
    asm("fma.rn.f32x2 %0, %1, %2, %3;" : "=l"(d) : "l"(a), "l"(b), "l"(c));
    return d;
}

// ---------------- setup kernels ----------------
__global__ void zero_kernel() {
    int i = blockIdx.x * 256 + threadIdx.x;
    if (i < NN) g_deg[i] = 0;
    if (i < 192) { g_bnsum[i] = 0.f; g_bnsq[i] = 0.f; }
}

__global__ void count_kernel(const int* __restrict__ dst) {
    int e = blockIdx.x * 256 + threadIdx.x;
    if (e < NE) atomicAdd(&g_deg[dst[e]], 1);
}

// Single-block exclusive scan over degrees; also computes deg^-1/2 (with self-loop)
// and resets fill cursors.
__global__ void scan_kernel() {
    const int T = 1024;
    int tid = threadIdx.x;
    int chunk = (NN + T - 1) / T;
    int lo = tid * chunk;
    int hi = lo + chunk; if (hi > NN) hi = NN;
    int s = 0;
    for (int i = lo; i < hi; i++) s += g_deg[i];

    __shared__ int warpsum[32];
    int lane = tid & 31, wid = tid >> 5;
    int incl = s;
    #pragma unroll
    for (int o = 1; o < 32; o <<= 1) {
        int v = __shfl_up_sync(0xffffffffu, incl, o);
        if (lane >= o) incl += v;
    }
    if (lane == 31) warpsum[wid] = incl;
    __syncthreads();
    if (wid == 0) {
        int w = warpsum[lane];
        int wincl = w;
        #pragma unroll
        for (int o = 1; o < 32; o <<= 1) {
            int v = __shfl_up_sync(0xffffffffu, wincl, o);
            if (lane >= o) wincl += v;
        }
        warpsum[lane] = wincl - w;  // exclusive
    }
    __syncthreads();
    int run = (incl - s) + warpsum[wid];
    for (int i = lo; i < hi; i++) {
        g_rowstart[i] = run;
        int d = g_deg[i];
        run += d;
        g_dinv[i] = rsqrtf((float)(d + 1));  // +1: self-loop
        g_fill[i] = 0;
    }
    if (tid == T - 1) g_rowstart[NN] = run;
}

__global__ void fill_kernel(const int* __restrict__ src, const int* __restrict__ dst) {
    int e = blockIdx.x * 256 + threadIdx.x;
    if (e < NE) {
        int d = dst[e];
        int pos = g_rowstart[d] + atomicAdd(&g_fill[d], 1);
        g_csr[pos] = src[e];
    }
}

// ---------------- layer-1 input aggregation (width 5; Â(XW) == (ÂX)W) ----------------
__global__ void prescale_kernel(const float* __restrict__ x, float* __restrict__ xs) {
    int t = blockIdx.x * 256 + threadIdx.x;
    if (t >= NN * 5) return;
    xs[t] = x[t] * g_dinv[t / 5];
}

__global__ void agg0_kernel(const float* __restrict__ xs, float* __restrict__ xa) {
    int t = blockIdx.x * 256 + threadIdx.x;
    if (t >= NN * 5) return;
    int node = t / 5, f = t - node * 5;
    float acc = xs[t];
    int s = g_rowstart[node], e = g_rowstart[node + 1];
    for (int j = s; j < e; j++)
        acc += __ldg(&xs[g_csr[j] * 5 + f]);
    xa[t] = g_dinv[node] * acc;
}

// h1 = relu(xa @ W1 + b1), [N,5] -> [N,256]
__global__ void gemm1_kernel(const float* __restrict__ xa, const float* __restrict__ W1,
                             const float* __restrict__ b1, float* __restrict__ h1) {
    __shared__ float w[5 * 256];
    __shared__ float bs[256];
    for (int i = threadIdx.x; i < 1280; i += 256) w[i] = W1[i];
    bs[threadIdx.x] = b1[threadIdx.x];
    __syncthreads();
    int idx = blockIdx.x * 256 + threadIdx.x;   // node*64 + chunk
    if (idx >= NN * 64) return;
    int node = idx >> 6;
    int c = (idx & 63) * 4;
    float xv[5];
    #pragma unroll
    for (int k = 0; k < 5; k++) xv[k] = xa[node * 5 + k];
    float4 acc = make_float4(bs[c], bs[c + 1], bs[c + 2], bs[c + 3]);
    #pragma unroll
    for (int k = 0; k < 5; k++) {
        acc.x = fmaf(xv[k], w[k * 256 + c + 0], acc.x);
        acc.y = fmaf(xv[k], w[k * 256 + c + 1], acc.y);
        acc.z = fmaf(xv[k], w[k * 256 + c + 2], acc.z);
        acc.w = fmaf(xv[k], w[k * 256 + c + 3], acc.w);
    }
    acc.x = fmaxf(acc.x, 0.f); acc.y = fmaxf(acc.y, 0.f);
    acc.z = fmaxf(acc.z, 0.f); acc.w = fmaxf(acc.w, 0.f);
    ((float4*)h1)[idx] = acc;
}

// ---------------- SGEMM v3: f32x2 packed FMA inner loop ----------------
// out[m,n] = rowscale[m] * sum_k affine(A[m,k]) * W[k,n]
template <int BM, int BN, int BK, int TM, int TN>
__global__ void gemm_kernel(const float* __restrict__ A, const float* __restrict__ W,
                            float* __restrict__ out, int M, int K, int N,
                            const float* __restrict__ affA, const float* __restrict__ affC,
                            const float* __restrict__ rowscale) {
    constexpr int THREADS = (BM / TM) * (BN / TN);
    constexpr int TN2 = TN / 2;
    __shared__ __align__(16) float As[BK][BM + 4];
    __shared__ __align__(16) float Bs[BK][BN];
    int tid = threadIdx.x;
    int tn = tid % (BN / TN);
    int tm = tid / (BN / TN);
    int rowBase = blockIdx.y * BM;
    int colBase = blockIdx.x * BN;

    unsigned long long acc2[TM][TN2];
    #pragma unroll
    for (int i = 0; i < TM; i++)
        #pragma unroll
        for (int j = 0; j < TN2; j++) acc2[i][j] = 0ull;

    for (int k0 = 0; k0 < K; k0 += BK) {
        // A tile: BM x BK, vectorized, stored transposed
        #pragma unroll
        for (int t = tid; t < BM * BK / 4; t += THREADS) {
            int m = t / (BK / 4);
            int kq = (t % (BK / 4)) * 4;
            int gr = rowBase + m;
            float4 v = make_float4(0.f, 0.f, 0.f, 0.f);
            if (gr < M) v = *(const float4*)&A[gr * K + k0 + kq];
            if (affA) {
                v.x = fmaf(v.x, affA[k0 + kq + 0], affC[k0 + kq + 0]);
                v.y = fmaf(v.y, affA[k0 + kq + 1], affC[k0 + kq + 1]);
                v.z = fmaf(v.z, affA[k0 + kq + 2], affC[k0 + kq + 2]);
                v.w = fmaf(v.w, affA[k0 + kq + 3], affC[k0 + kq + 3]);
            }
            As[kq + 0][m] = v.x;
            As[kq + 1][m] = v.y;
            As[kq + 2][m] = v.z;
            As[kq + 3][m] = v.w;
        }
        // B tile: BK x BN
        #pragma unroll
        for (int t = tid; t < BK * BN / 4; t += THREADS) {
            int k = t / (BN / 4);
            int nq = (t % (BN / 4)) * 4;
            *(float4*)&Bs[k][nq] = *(const float4*)&W[(k0 + k) * N + colBase + nq];
        }
        __syncthreads();
        #pragma unroll
        for (int k = 0; k < BK; k++) {
            float a[TM];
            unsigned long long b2[TN2];
            #pragma unroll
            for (int i = 0; i < TM; i += 4)
                *(float4*)&a[i] = *(const float4*)&As[k][tm * TM + i];
            #pragma unroll
            for (int j = 0; j < TN2; j++)
                b2[j] = *(const unsigned long long*)&Bs[k][tn * TN + j * 2];
            #pragma unroll
            for (int i = 0; i < TM; i++) {
                unsigned long long av = pack2(a[i], a[i]);
                #pragma unroll
                for (int j = 0; j < TN2; j++)
                    acc2[i][j] = fma2(av, b2[j], acc2[i][j]);
            }
        }
        __syncthreads();
    }
    #pragma unroll
    for (int i = 0; i < TM; i++) {
        int gr = rowBase + tm * TM + i;
        if (gr < M) {
            float rs = rowscale ? rowscale[gr] : 1.f;
            #pragma unroll
            for (int j = 0; j < TN2; j += 2) {
                float x0, x1, x2, x3;
                unpack2(acc2[i][j], x0, x1);
                unpack2(acc2[i][j + 1], x2, x3);
                float4 v = make_float4(x0 * rs, x1 * rs, x2 * rs, x3 * rs);
                *(float4*)&out[gr * N + colBase + tn * TN + j * 2] = v;
            }
        }
    }
}

// ---------------- CSR aggregation: out[i] = relu(dinv[i]*(u[i] + sum_src u[src]) + b) ----------------
template <int F>
__global__ void agg_kernel(const float* __restrict__ u, const float* __restrict__ bias,
                           float* __restrict__ out) {
    constexpr int CH = F / 4;          // float4 lanes per node
    constexpr int NPB = 256 / CH;      // nodes per block
    int node = blockIdx.x * NPB + threadIdx.x / CH;
    int lane = threadIdx.x % CH;
    if (node >= NN) return;
    const float4* u4 = (const float4*)u;
    float4 acc = u4[node * CH + lane];   // self-loop term
    float4 accB = make_float4(0.f, 0.f, 0.f, 0.f);
    int s = g_rowstart[node];
    int e = g_rowstart[node + 1];
    int j = s;
    for (; j + 2 <= e; j += 2) {
        int s0 = __ldg(&g_csr[j]);
        int s1 = __ldg(&g_csr[j + 1]);
        float4 v0 = __ldg(&u4[s0 * CH + lane]);
        float4 v1 = __ldg(&u4[s1 * CH + lane]);
        acc.x += v0.x;  acc.y += v0.y;  acc.z += v0.z;  acc.w += v0.w;
        accB.x += v1.x; accB.y += v1.y; accB.z += v1.z; accB.w += v1.w;
    }
    if (j < e) {
        float4 v = __ldg(&u4[__ldg(&g_csr[j]) * CH + lane]);
        acc.x += v.x; acc.y += v.y; acc.z += v.z; acc.w += v.w;
    }
    acc.x += accB.x; acc.y += accB.y; acc.z += accB.z; acc.w += accB.w;
    float d = g_dinv[node];
    float4 b = ((const float4*)bias)[lane];
    float4 o;
    o.x = fmaxf(fmaf(d, acc.x, b.x), 0.f);
    o.y = fmaxf(fmaf(d, acc.y, b.y), 0.f);
    o.z = fmaxf(fmaf(d, acc.z, b.z), 0.f);
    o.w = fmaxf(fmaf(d, acc.w, b.w), 0.f);
    ((float4*)out)[node * CH + lane] = o;
}

// ---------------- batchnorm stats (sum / sumsq per feature) ----------------
__global__ void bn_stats(const float* __restrict__ h, int F,
                         float* __restrict__ sums, float* __restrict__ sqs) {
    __shared__ float ss[256], sq[256];
    int tid = threadIdx.x;
    long long idx = (long long)blockIdx.x * 256 + tid;
    long long total = (long long)NN * F;
    long long stride = (long long)gridDim.x * 256;   // multiple of F (F in {64,128})
    float s = 0.f, q = 0.f;
    for (; idx < total; idx += stride) {
        float v = h[idx];
        s += v; q += v * v;
    }
    ss[tid] = s; sq[tid] = q;
    __syncthreads();
    for (int off = 128; off >= F; off >>= 1) {
        if (tid < off) { ss[tid] += ss[tid + off]; sq[tid] += sq[tid + off]; }
        __syncthreads();
    }
    if (tid < F) {
        atomicAdd(&sums[tid], ss[tid]);
        atomicAdd(&sqs[tid], sq[tid]);
    }
}

__global__ void bn_finalize(const float* __restrict__ sums, const float* __restrict__ sqs,
                            const float* __restrict__ gamma, const float* __restrict__ beta,
                            float* __restrict__ a, float* __restrict__ c, int F) {
    int f = threadIdx.x;
    if (f < F) {
        float mean = sums[f] * (1.0f / NN);
        float var = sqs[f] * (1.0f / NN) - mean * mean;
        float aa = gamma[f] * rsqrtf(var + EPSV);
        a[f] = aa;
        c[f] = beta[f] - mean * aa;
    }
}

// ---------------- global mean pool (batch is sorted -> binary search per graph) ----------------
__device__ __forceinline__ int lower_bound_i(const int* arr, int n, int val) {
    int lo = 0, hi = n;
    while (lo < hi) {
        int mid = (lo + hi) >> 1;
        if (arr[mid] < val) lo = mid + 1; else hi = mid;
    }
    return lo;
}

__global__ void pool_kernel(const int* __restrict__ batch, const float* __restrict__ h) {
    int g = blockIdx.x;
    int start = lower_bound_i(batch, NN, g);
    int end   = lower_bound_i(batch, NN, g + 1);
    int tid = threadIdx.x;
    int f = tid & 63, r0 = tid >> 6;
    float s = 0.f;
    for (int r = start + r0; r < end; r += 4) s += h[r * 64 + f];
    __shared__ float sm[256];
    sm[tid] = s;
    __syncthreads();
    if (tid < 128) sm[tid] += sm[tid + 128];
    __syncthreads();
    if (tid < 64) g_pool[g * 64 + tid] = sm[tid] + sm[tid + 64];
    if (tid == 0) g_cnt[g] = end - start;
}

// ---------------- final: bn2 (affine, folded) + mean + FC ----------------
__global__ void final_kernel(const float* __restrict__ Wfc, const float* __restrict__ bfc,
                             float* __restrict__ out) {
    int t = threadIdx.x;
    if (t >= NG * 6) return;
    int g = t / 6, cl = t % 6;
    float cnt = (float)g_cnt[g];
    float inv = 1.f / fmaxf(cnt, 1.f);
    float acc = bfc[cl];
    #pragma unroll
    for (int j = 0; j < 64; j++) {
        float p = fmaf(g_a[128 + j], g_pool[g * 64 + j] * inv, g_c[128 + j]);
        acc = fmaf(p, Wfc[j * 6 + cl], acc);
    }
    out[g * 6 + cl] = acc;
}

// ---------------- host orchestration ----------------
extern "C" void kernel_launch(void* const* d_in, const int* in_sizes, int n_in,
                              void* d_out, int out_size) {
    const float* x      = (const float*)d_in[0];
    const int*   edge   = (const int*)d_in[1];   // int32 (JAX x64 disabled)
    const int*   batch  = (const int*)d_in[2];   // int32
    const float* W1     = (const float*)d_in[3];
    const float* b1     = (const float*)d_in[4];
    const float* W2     = (const float*)d_in[5];
    const float* b2     = (const float*)d_in[6];
    const float* gamma1 = (const float*)d_in[7];
    const float* beta1  = (const float*)d_in[8];
    const float* W3     = (const float*)d_in[9];
    const float* b3     = (const float*)d_in[10];
    const float* gamma2 = (const float*)d_in[11];
    const float* beta2  = (const float*)d_in[12];
    const float* Wfc    = (const float*)d_in[13];
    const float* bfc    = (const float*)d_in[14];
    float* out = (float*)d_out;

    const int* srcp = edge;
    const int* dstp = edge + NE;

    float *bufA, *bufB, *dinv, *bnsum, *bnsq, *aArr, *cArr;
    cudaGetSymbolAddress((void**)&bufA,  g_bufA);
    cudaGetSymbolAddress((void**)&bufB,  g_bufB);
    cudaGetSymbolAddress((void**)&dinv,  g_dinv);
    cudaGetSymbolAddress((void**)&bnsum, g_bnsum);
    cudaGetSymbolAddress((void**)&bnsq,  g_bnsq);
    cudaGetSymbolAddress((void**)&aArr,  g_a);
    cudaGetSymbolAddress((void**)&cArr,  g_c);

    // graph preprocessing (once per launch, reused by all 3 layers)
    zero_kernel<<<(NN + 255) / 256, 256>>>();
    count_kernel<<<(NE + 255) / 256, 256>>>(dstp);
    scan_kernel<<<1, 1024>>>();
    fill_kernel<<<(NE + 255) / 256, 256>>>(srcp, dstp);

    // layer 1 (reassociated): xa = Â x (width 5), then h1 = relu(xa @ W1 + b1)
    prescale_kernel<<<(NN * 5 + 255) / 256, 256>>>(x, bufB);          // xs -> bufB
    agg0_kernel<<<(NN * 5 + 255) / 256, 256>>>(bufB, bufA);           // xa -> bufA
    gemm1_kernel<<<(NN * 64 + 255) / 256, 256>>>(bufA, W1, b1, bufB); // h1 -> bufB

    // layer 2: u2 = dinv * (h1 @ W2) -> bufA; agg -> h2 -> bufB; bn1 stats
    gemm_kernel<128, 128, 16, 8, 8><<<dim3(1, (NN + 127) / 128), 256>>>(
        bufB, W2, bufA, NN, 256, 128, nullptr, nullptr, dinv);
    agg_kernel<128><<<(NN + 7) / 8, 256>>>(bufA, b2, bufB);
    bn_stats<<<296, 256>>>(bufB, 128, bnsum, bnsq);
    bn_finalize<<<1, 128>>>(bnsum, bnsq, gamma1, beta1, aArr, cArr, 128);

    // layer 3: bn1 folded into A-load; u3 = dinv * (bn1(h2) @ W3) -> bufA; agg -> h3 -> bufB
    gemm_kernel<128, 64, 16, 8, 8><<<dim3(1, (NN + 127) / 128), 128>>>(
        bufB, W3, bufA, NN, 128, 64, aArr, cArr, dinv);
    agg_kernel<64><<<(NN + 15) / 16, 256>>>(bufA, b3, bufB);
    bn_stats<<<296, 256>>>(bufB, 64, bnsum + 128, bnsq + 128);
    bn_finalize<<<1, 64>>>(bnsum + 128, bnsq + 128, gamma2, beta2, aArr + 128, cArr + 128, 64);

    // pool + bn2(folded) + FC
    pool_kernel<<<NG, 256>>>(batch, bufB);
    final_kernel<<<1, 512>>>(Wfc, bfc, out);
}

// round 5
// speedup vs baseline: 1.5769x; 1.1632x over previous
#include <cuda_runtime.h>
#include <cstdint>

#define NN 50000
#define NE 800000
#define NG 64
#define EPSV 1e-5f

// ---------------- scratch (device globals; no allocations allowed) ----------------
__device__ float g_bufA[NN * 256];
__device__ float g_bufB[NN * 256];
__device__ float g_dinv[NN];
__device__ int   g_deg[NN];
__device__ int   g_rowstart[NN + 1];
__device__ int   g_fill[NN];
__device__ int   g_csr[NE];
__device__ float g_bnsum[192];
__device__ float g_bnsq[192];
__device__ float g_a[192];   // [0:128) bn1 scale, [128:192) bn2 scale
__device__ float g_c[192];   // matching shifts
__device__ float g_pool[NG * 64];
__device__ int   g_cnt[NG];

// ---------------- TF32 helpers ----------------
__device__ __forceinline__ unsigned cvt_tf32(float v) {
    unsigned r;
    asm("cvt.rna.tf32.f32 %0, %1;" : "=r"(r) : "f"(v));
    return r;
}
__device__ __forceinline__ void mma_tf32(float* c, const unsigned* a, const unsigned* b) {
    asm volatile(
        "mma.sync.aligned.m16n8k8.row.col.f32.tf32.tf32.f32 "
        "{%0,%1,%2,%3}, {%4,%5,%6,%7}, {%8,%9}, {%0,%1,%2,%3};"
        : "+f"(c[0]), "+f"(c[1]), "+f"(c[2]), "+f"(c[3])
        : "r"(a[0]), "r"(a[1]), "r"(a[2]), "r"(a[3]), "r"(b[0]), "r"(b[1]));
}

// ---------------- setup kernels ----------------
__global__ void zero_kernel() {
    int i = blockIdx.x * 256 + threadIdx.x;
    if (i < NN) g_deg[i] = 0;
    if (i < 192) { g_bnsum[i] = 0.f; g_bnsq[i] = 0.f; }
    if (i < NG * 64) g_pool[i] = 0.f;
}

__global__ void count_kernel(const int* __restrict__ dst) {
    int e = blockIdx.x * 256 + threadIdx.x;
    if (e < NE) atomicAdd(&g_deg[dst[e]], 1);
}

// Single-block exclusive scan over degrees; also computes deg^-1/2 (with self-loop)
// and resets fill cursors.
__global__ void scan_kernel() {
    const int T = 1024;
    int tid = threadIdx.x;
    int chunk = (NN + T - 1) / T;
    int lo = tid * chunk;
    int hi = lo + chunk; if (hi > NN) hi = NN;
    int s = 0;
    for (int i = lo; i < hi; i++) s += g_deg[i];

    __shared__ int warpsum[32];
    int lane = tid & 31, wid = tid >> 5;
    int incl = s;
    #pragma unroll
    for (int o = 1; o < 32; o <<= 1) {
        int v = __shfl_up_sync(0xffffffffu, incl, o);
        if (lane >= o) incl += v;
    }
    if (lane == 31) warpsum[wid] = incl;
    __syncthreads();
    if (wid == 0) {
        int w = warpsum[lane];
        int wincl = w;
        #pragma unroll
        for (int o = 1; o < 32; o <<= 1) {
            int v = __shfl_up_sync(0xffffffffu, wincl, o);
            if (lane >= o) wincl += v;
        }
        warpsum[lane] = wincl - w;  // exclusive
    }
    __syncthreads();
    int run = (incl - s) + warpsum[wid];
    for (int i = lo; i < hi; i++) {
        g_rowstart[i] = run;
        int d = g_deg[i];
        run += d;
        g_dinv[i] = rsqrtf((float)(d + 1));  // +1: self-loop
        g_fill[i] = 0;
    }
    if (tid == T - 1) g_rowstart[NN] = run;
}

__global__ void fill_kernel(const int* __restrict__ src, const int* __restrict__ dst) {
    int e = blockIdx.x * 256 + threadIdx.x;
    if (e < NE) {
        int d = dst[e];
        int pos = g_rowstart[d] + atomicAdd(&g_fill[d], 1);
        g_csr[pos] = src[e];
    }
}

// ---------------- layer-1 input aggregation (width 5; Â(XW) == (ÂX)W) ----------------
// xa[i] = dinv[i] * (dinv[i]*x[i] + sum_src dinv[src]*x[src])   (prescale fused)
__global__ void agg0_kernel(const float* __restrict__ x, float* __restrict__ xa) {
    int t = blockIdx.x * 256 + threadIdx.x;
    if (t >= NN * 5) return;
    int node = t / 5, f = t - node * 5;
    float dn = g_dinv[node];
    float acc = x[t] * dn;
    int s = g_rowstart[node], e = g_rowstart[node + 1];
    for (int j = s; j < e; j++) {
        int src = g_csr[j];
        acc += __ldg(&x[src * 5 + f]) * __ldg(&g_dinv[src]);
    }
    xa[t] = dn * acc;
}

// h1 = relu(xa @ W1 + b1), [N,5] -> [N,256]
__global__ void gemm1_kernel(const float* __restrict__ xa, const float* __restrict__ W1,
                             const float* __restrict__ b1, float* __restrict__ h1) {
    __shared__ float w[5 * 256];
    __shared__ float bs[256];
    for (int i = threadIdx.x; i < 1280; i += 256) w[i] = W1[i];
    bs[threadIdx.x] = b1[threadIdx.x];
    __syncthreads();
    int idx = blockIdx.x * 256 + threadIdx.x;   // node*64 + chunk
    if (idx >= NN * 64) return;
    int node = idx >> 6;
    int c = (idx & 63) * 4;
    float xv[5];
    #pragma unroll
    for (int k = 0; k < 5; k++) xv[k] = xa[node * 5 + k];
    float4 acc = make_float4(bs[c], bs[c + 1], bs[c + 2], bs[c + 3]);
    #pragma unroll
    for (int k = 0; k < 5; k++) {
        acc.x = fmaf(xv[k], w[k * 256 + c + 0], acc.x);
        acc.y = fmaf(xv[k], w[k * 256 + c + 1], acc.y);
        acc.z = fmaf(xv[k], w[k * 256 + c + 2], acc.z);
        acc.w = fmaf(xv[k], w[k * 256 + c + 3], acc.w);
    }
    acc.x = fmaxf(acc.x, 0.f); acc.y = fmaxf(acc.y, 0.f);
    acc.z = fmaxf(acc.z, 0.f); acc.w = fmaxf(acc.w, 0.f);
    ((float4*)h1)[idx] = acc;
}

// ---------------- TF32 tensor-core GEMM ----------------
// out[m,n] = rowscale[m] * sum_k affine(A[m,k]) * W[k,n]
// Block tile BM x BN, warp tile WM(=32) x WN(=64), mma m16n8k8.
template <int BM, int BN, int BK, int WM, int WN>
__global__ void gemm_tf32_kernel(const float* __restrict__ A, const float* __restrict__ W,
                                 float* __restrict__ out, int M, int K, int N,
                                 const float* __restrict__ affA, const float* __restrict__ affC,
                                 const float* __restrict__ rowscale) {
    constexpr int WARPS_M = BM / WM;
    constexpr int WARPS_N = BN / WN;
    constexpr int THREADS = WARPS_M * WARPS_N * 32;
    constexpr int MT = WM / 16;   // m16 subtiles per warp (2)
    constexpr int NT = WN / 8;    // n8 subtiles per warp (8)

    __shared__ unsigned As[BK][BM + 4];   // [k][m], tf32 bits
    __shared__ unsigned Bs[BK][BN + 4];   // [k][n], tf32 bits

    int tid = threadIdx.x;
    int lane = tid & 31;
    int wid = tid >> 5;
    int warpM = wid % WARPS_M;
    int warpN = wid / WARPS_M;
    int g = lane >> 2;        // groupID (0..7)
    int t = lane & 3;         // thread-in-group (0..3)
    int rowBase = blockIdx.y * BM;
    int colBase = blockIdx.x * BN;

    float acc[MT][NT][4];
    #pragma unroll
    for (int i = 0; i < MT; i++)
        #pragma unroll
        for (int j = 0; j < NT; j++)
            #pragma unroll
            for (int q = 0; q < 4; q++) acc[i][j][q] = 0.f;

    for (int k0 = 0; k0 < K; k0 += BK) {
        // A tile: BM x BK, stored transposed [k][m]
        #pragma unroll
        for (int it = tid; it < BM * BK / 4; it += THREADS) {
            int m = it / (BK / 4);
            int kq = (it % (BK / 4)) * 4;
            int gr = rowBase + m;
            float4 v = make_float4(0.f, 0.f, 0.f, 0.f);
            if (gr < M) {
                v = *(const float4*)&A[gr * K + k0 + kq];
                if (affA) {
                    v.x = fmaf(v.x, affA[k0 + kq + 0], affC[k0 + kq + 0]);
                    v.y = fmaf(v.y, affA[k0 + kq + 1], affC[k0 + kq + 1]);
                    v.z = fmaf(v.z, affA[k0 + kq + 2], affC[k0 + kq + 2]);
                    v.w = fmaf(v.w, affA[k0 + kq + 3], affC[k0 + kq + 3]);
                }
            }
            As[kq + 0][m] = cvt_tf32(v.x);
            As[kq + 1][m] = cvt_tf32(v.y);
            As[kq + 2][m] = cvt_tf32(v.z);
            As[kq + 3][m] = cvt_tf32(v.w);
        }
        // B tile: BK x BN
        #pragma unroll
        for (int it = tid; it < BK * BN / 4; it += THREADS) {
            int k = it / (BN / 4);
            int nq = (it % (BN / 4)) * 4;
            float4 v = *(const float4*)&W[(k0 + k) * N + colBase + nq];
            Bs[k][nq + 0] = cvt_tf32(v.x);
            Bs[k][nq + 1] = cvt_tf32(v.y);
            Bs[k][nq + 2] = cvt_tf32(v.z);
            Bs[k][nq + 3] = cvt_tf32(v.w);
        }
        __syncthreads();
        #pragma unroll
        for (int kk = 0; kk < BK; kk += 8) {
            unsigned a[MT][4], b[NT][2];
            #pragma unroll
            for (int mt = 0; mt < MT; mt++) {
                int mb = warpM * WM + mt * 16;
                a[mt][0] = As[kk + t][mb + g];
                a[mt][1] = As[kk + t][mb + g + 8];
                a[mt][2] = As[kk + t + 4][mb + g];
                a[mt][3] = As[kk + t + 4][mb + g + 8];
            }
            #pragma unroll
            for (int nt = 0; nt < NT; nt++) {
                int nb = warpN * WN + nt * 8;
                b[nt][0] = Bs[kk + t][nb + g];
                b[nt][1] = Bs[kk + t + 4][nb + g];
            }
            #pragma unroll
            for (int mt = 0; mt < MT; mt++)
                #pragma unroll
                for (int nt = 0; nt < NT; nt++)
                    mma_tf32(acc[mt][nt], a[mt], b[nt]);
        }
        __syncthreads();
    }

    // Epilogue: rowscale + store (c0,c1 row r0; c2,c3 row r0+8)
    #pragma unroll
    for (int mt = 0; mt < MT; mt++) {
        int r0 = rowBase + warpM * WM + mt * 16 + g;
        int r1 = r0 + 8;
        float rs0 = (r0 < M) ? (rowscale ? rowscale[r0] : 1.f) : 0.f;
        float rs1 = (r1 < M) ? (rowscale ? rowscale[r1] : 1.f) : 0.f;
        #pragma unroll
        for (int nt = 0; nt < NT; nt++) {
            int col = colBase + warpN * WN + nt * 8 + 2 * t;
            if (r0 < M) {
                float2 v = make_float2(acc[mt][nt][0] * rs0, acc[mt][nt][1] * rs0);
                *(float2*)&out[r0 * N + col] = v;
            }
            if (r1 < M) {
                float2 v = make_float2(acc[mt][nt][2] * rs1, acc[mt][nt][3] * rs1);
                *(float2*)&out[r1 * N + col] = v;
            }
        }
    }
}

// ---------------- CSR aggregation: out[i] = relu(dinv[i]*(u[i] + sum_src u[src]) + b) ----------------
template <int F>
__global__ void agg_kernel(const float* __restrict__ u, const float* __restrict__ bias,
                           float* __restrict__ out) {
    constexpr int CH = F / 4;          // float4 lanes per node
    constexpr int NPB = 256 / CH;      // nodes per block
    int node = blockIdx.x * NPB + threadIdx.x / CH;
    int lane = threadIdx.x % CH;
    if (node >= NN) return;
    const float4* u4 = (const float4*)u;
    float4 acc = u4[node * CH + lane];   // self-loop term
    float4 accB = make_float4(0.f, 0.f, 0.f, 0.f);
    int s = g_rowstart[node];
    int e = g_rowstart[node + 1];
    int j = s;
    for (; j + 2 <= e; j += 2) {
        int s0 = __ldg(&g_csr[j]);
        int s1 = __ldg(&g_csr[j + 1]);
        float4 v0 = __ldg(&u4[s0 * CH + lane]);
        float4 v1 = __ldg(&u4[s1 * CH + lane]);
        acc.x += v0.x;  acc.y += v0.y;  acc.z += v0.z;  acc.w += v0.w;
        accB.x += v1.x; accB.y += v1.y; accB.z += v1.z; accB.w += v1.w;
    }
    if (j < e) {
        float4 v = __ldg(&u4[__ldg(&g_csr[j]) * CH + lane]);
        acc.x += v.x; acc.y += v.y; acc.z += v.z; acc.w += v.w;
    }
    acc.x += accB.x; acc.y += accB.y; acc.z += accB.z; acc.w += accB.w;
    float d = g_dinv[node];
    float4 b = ((const float4*)bias)[lane];
    float4 o;
    o.x = fmaxf(fmaf(d, acc.x, b.x), 0.f);
    o.y = fmaxf(fmaf(d, acc.y, b.y), 0.f);
    o.z = fmaxf(fmaf(d, acc.z, b.z), 0.f);
    o.w = fmaxf(fmaf(d, acc.w, b.w), 0.f);
    ((float4*)out)[node * CH + lane] = o;
}

// ---------------- batchnorm stats (sum / sumsq per feature) ----------------
__global__ void bn_stats(const float* __restrict__ h, int F,
                         float* __restrict__ sums, float* __restrict__ sqs) {
    __shared__ float ss[256], sq[256];
    int tid = threadIdx.x;
    long long idx = (long long)blockIdx.x * 256 + tid;
    long long total = (long long)NN * F;
    long long stride = (long long)gridDim.x * 256;   // multiple of F (F in {64,128})
    float s = 0.f, q = 0.f;
    for (; idx < total; idx += stride) {
        float v = h[idx];
        s += v; q += v * v;
    }
    ss[tid] = s; sq[tid] = q;
    __syncthreads();
    for (int off = 128; off >= F; off >>= 1) {
        if (tid < off) { ss[tid] += ss[tid + off]; sq[tid] += sq[tid + off]; }
        __syncthreads();
    }
    if (tid < F) {
        atomicAdd(&sums[tid], ss[tid]);
        atomicAdd(&sqs[tid], sq[tid]);
    }
}

__global__ void bn_finalize(const float* __restrict__ sums, const float* __restrict__ sqs,
                            const float* __restrict__ gamma, const float* __restrict__ beta,
                            float* __restrict__ a, float* __restrict__ c, int F) {
    int f = threadIdx.x;
    if (f < F) {
        float mean = sums[f] * (1.0f / NN);
        float var = sqs[f] * (1.0f / NN) - mean * mean;
        float aa = gamma[f] * rsqrtf(var + EPSV);
        a[f] = aa;
        c[f] = beta[f] - mean * aa;
    }
}

// ---------------- global mean pool (batch is sorted -> binary search per graph) ----------------
__device__ __forceinline__ int lower_bound_i(const int* arr, int n, int val) {
    int lo = 0, hi = n;
    while (lo < hi) {
        int mid = (lo + hi) >> 1;
        if (arr[mid] < val) lo = mid + 1; else hi = mid;
    }
    return lo;
}

// grid (NG, 4): 4 partial blocks per graph, merged via atomics into g_pool.
__global__ void pool_kernel(const int* __restrict__ batch, const float* __restrict__ h) {
    int g = blockIdx.x, part = blockIdx.y;
    int start = lower_bound_i(batch, NN, g);
    int end   = lower_bound_i(batch, NN, g + 1);
    int tid = threadIdx.x;
    int f = tid & 63, r0 = tid >> 6;   // r0 in 0..3
    float s = 0.f;
    for (int r = start + part * 4 + r0; r < end; r += 16) s += h[r * 64 + f];
    __shared__ float sm[256];
    sm[tid] = s;
    __syncthreads();
    if (tid < 128) sm[tid] += sm[tid + 128];
    __syncthreads();
    if (tid < 64) atomicAdd(&g_pool[g * 64 + tid], sm[tid] + sm[tid + 64]);
    if (part == 0 && tid == 0) g_cnt[g] = end - start;
}

// ---------------- final: bn2 (affine, folded) + mean + FC ----------------
__global__ void final_kernel(const float* __restrict__ Wfc, const float* __restrict__ bfc,
                             float* __restrict__ out) {
    int t = threadIdx.x;
    if (t >= NG * 6) return;
    int g = t / 6, cl = t % 6;
    float cnt = (float)g_cnt[g];
    float inv = 1.f / fmaxf(cnt, 1.f);
    float acc = bfc[cl];
    #pragma unroll
    for (int j = 0; j < 64; j++) {
        float p = fmaf(g_a[128 + j], g_pool[g * 64 + j] * inv, g_c[128 + j]);
        acc = fmaf(p, Wfc[j * 6 + cl], acc);
    }
    out[g * 6 + cl] = acc;
}

// ---------------- host orchestration ----------------
extern "C" void kernel_launch(void* const* d_in, const int* in_sizes, int n_in,
                              void* d_out, int out_size) {
    const float* x      = (const float*)d_in[0];
    const int*   edge   = (const int*)d_in[1];   // int32 (JAX x64 disabled)
    const int*   batch  = (const int*)d_in[2];   // int32
    const float* W1     = (const float*)d_in[3];
    const float* b1     = (const float*)d_in[4];
    const float* W2     = (const float*)d_in[5];
    const float* b2     = (const float*)d_in[6];
    const float* gamma1 = (const float*)d_in[7];
    const float* beta1  = (const float*)d_in[8];
    const float* W3     = (const float*)d_in[9];
    const float* b3     = (const float*)d_in[10];
    const float* gamma2 = (const float*)d_in[11];
    const float* beta2  = (const float*)d_in[12];
    const float* Wfc    = (const float*)d_in[13];
    const float* bfc    = (const float*)d_in[14];
    float* out = (float*)d_out;

    const int* srcp = edge;
    const int* dstp = edge + NE;

    float *bufA, *bufB, *dinv, *bnsum, *bnsq, *aArr, *cArr;
    cudaGetSymbolAddress((void**)&bufA,  g_bufA);
    cudaGetSymbolAddress((void**)&bufB,  g_bufB);
    cudaGetSymbolAddress((void**)&dinv,  g_dinv);
    cudaGetSymbolAddress((void**)&bnsum, g_bnsum);
    cudaGetSymbolAddress((void**)&bnsq,  g_bnsq);
    cudaGetSymbolAddress((void**)&aArr,  g_a);
    cudaGetSymbolAddress((void**)&cArr,  g_c);

    // graph preprocessing (once per launch, reused by all 3 layers)
    zero_kernel<<<(NN + 255) / 256, 256>>>();
    count_kernel<<<(NE + 255) / 256, 256>>>(dstp);
    scan_kernel<<<1, 1024>>>();
    fill_kernel<<<(NE + 255) / 256, 256>>>(srcp, dstp);

    // layer 1 (reassociated): xa = Â x (width 5), then h1 = relu(xa @ W1 + b1)
    agg0_kernel<<<(NN * 5 + 255) / 256, 256>>>(x, bufA);              // xa -> bufA
    gemm1_kernel<<<(NN * 64 + 255) / 256, 256>>>(bufA, W1, b1, bufB); // h1 -> bufB

    // layer 2 (TF32): u2 = dinv * (h1 @ W2) -> bufA; agg -> h2 -> bufB; bn1 stats
    gemm_tf32_kernel<128, 128, 32, 32, 64><<<dim3(1, (NN + 127) / 128), 256>>>(
        bufB, W2, bufA, NN, 256, 128, nullptr, nullptr, dinv);
    agg_kernel<128><<<(NN + 7) / 8, 256>>>(bufA, b2, bufB);
    bn_stats<<<296, 256>>>(bufB, 128, bnsum, bnsq);
    bn_finalize<<<1, 128>>>(bnsum, bnsq, gamma1, beta1, aArr, cArr, 128);

    // layer 3 (TF32): bn1 folded into A-load; u3 = dinv * (bn1(h2) @ W3) -> bufA; agg -> h3 -> bufB
    gemm_tf32_kernel<128, 64, 32, 32, 64><<<dim3(1, (NN + 127) / 128), 128>>>(
        bufB, W3, bufA, NN, 128, 64, aArr, cArr, dinv);
    agg_kernel<64><<<(NN + 15) / 16, 256>>>(bufA, b3, bufB);
    bn_stats<<<296, 256>>>(bufB, 64, bnsum + 128, bnsq + 128);
    bn_finalize<<<1, 64>>>(bnsum + 128, bnsq + 128, gamma2, beta2, aArr + 128, cArr + 128, 64);

    // pool + bn2(folded) + FC
    pool_kernel<<<dim3(NG, 4), 256>>>(batch, bufB);
    final_kernel<<<1, 512>>>(Wfc, bfc, out);
}

// round 6
// speedup vs baseline: 2.0826x; 1.3207x over previous
#include <cuda_runtime.h>
#include <cstdint>

#define NN 50000
#define NE 800000
#define NG 64
#define EPSV 1e-5f

// ---------------- scratch (device globals; no allocations allowed) ----------------
__device__ float g_bufA[NN * 256];
__device__ float g_bufB[NN * 256];
__device__ float g_dinv[NN];
__device__ __align__(16) int g_deg[NN + 8];
__device__ __align__(16) int g_rowstart[NN + 8];
__device__ int   g_fill[NN];
__device__ int   g_csr[NE];
__device__ float g_bnsum[192];
__device__ float g_bnsq[192];
__device__ float g_a[192];   // [0:128) bn1 scale, [128:192) bn2 scale
__device__ float g_c[192];   // matching shifts
__device__ float g_pool[NG * 64];
__device__ int   g_cnt[NG];
__device__ int   g_ctr[4];   // last-block counters: 0=bn1, 1=bn2, 2=pool

// ---------------- TF32 helpers ----------------
__device__ __forceinline__ unsigned cvt_tf32(float v) {
    unsigned r;
    asm("cvt.rna.tf32.f32 %0, %1;" : "=r"(r) : "f"(v));
    return r;
}
__device__ __forceinline__ void mma_tf32(float* c, const unsigned* a, const unsigned* b) {
    asm volatile(
        "mma.sync.aligned.m16n8k8.row.col.f32.tf32.tf32.f32 "
        "{%0,%1,%2,%3}, {%4,%5,%6,%7}, {%8,%9}, {%0,%1,%2,%3};"
        : "+f"(c[0]), "+f"(c[1]), "+f"(c[2]), "+f"(c[3])
        : "r"(a[0]), "r"(a[1]), "r"(a[2]), "r"(a[3]), "r"(b[0]), "r"(b[1]));
}

// ---------------- setup kernels ----------------
__global__ void zero_kernel() {
    int i = blockIdx.x * 256 + threadIdx.x;
    if (i < NN) g_deg[i] = 0;
    if (i < 192) { g_bnsum[i] = 0.f; g_bnsq[i] = 0.f; }
    if (i < NG * 64) g_pool[i] = 0.f;
    if (i < 4) g_ctr[i] = 0;
}

__global__ void count_kernel(const int* __restrict__ dst) {
    int e = (blockIdx.x * 256 + threadIdx.x) * 2;
    if (e < NE) {   // NE even -> pairs always complete
        int2 d = *(const int2*)&dst[e];
        atomicAdd(&g_deg[d.x], 1);
        atomicAdd(&g_deg[d.y], 1);
    }
}

// Single-block exclusive scan over degrees -> rowstart (int4-vectorized).
__global__ void scan_kernel() {
    const int CH = 52;                 // multiple of 4
    int tid = threadIdx.x;
    int lo = tid * CH; if (lo > NN) lo = NN;
    int hi = lo + CH;  if (hi > NN) hi = NN;
    int s = 0;
    for (int i = lo; i < hi; i += 4) {
        int4 d = *(const int4*)&g_deg[i];
        s += d.x + d.y + d.z + d.w;
    }

    __shared__ int warpsum[32];
    int lane = tid & 31, wid = tid >> 5;
    int incl = s;
    #pragma unroll
    for (int o = 1; o < 32; o <<= 1) {
        int v = __shfl_up_sync(0xffffffffu, incl, o);
        if (lane >= o) incl += v;
    }
    if (lane == 31) warpsum[wid] = incl;
    __syncthreads();
    if (wid == 0) {
        int w = warpsum[lane];
        int wincl = w;
        #pragma unroll
        for (int o = 1; o < 32; o <<= 1) {
            int v = __shfl_up_sync(0xffffffffu, wincl, o);
            if (lane >= o) wincl += v;
        }
        warpsum[lane] = wincl - w;  // exclusive across warps
    }
    __syncthreads();
    int run = (incl - s) + warpsum[wid];
    for (int i = lo; i < hi; i += 4) {
        int4 d = *(const int4*)&g_deg[i];
        int4 rs;
        rs.x = run;
        rs.y = run + d.x;
        rs.z = run + d.x + d.y;
        rs.w = run + d.x + d.y + d.z;
        run += d.x + d.y + d.z + d.w;
        *(int4*)&g_rowstart[i] = rs;
    }
    if (lo < NN && hi == NN) g_rowstart[NN] = run;
}

// full-chip: dinv + fill cursors (moved out of the single-SM scan)
__global__ void prep_kernel() {
    int i = blockIdx.x * 256 + threadIdx.x;
    if (i < NN) {
        g_dinv[i] = rsqrtf((float)(g_deg[i] + 1));  // +1: self-loop
        g_fill[i] = 0;
    }
}

__global__ void fill_kernel(const int* __restrict__ src, const int* __restrict__ dst) {
    int e = (blockIdx.x * 256 + threadIdx.x) * 2;
    if (e < NE) {
        int2 d = *(const int2*)&dst[e];
        int2 sc = *(const int2*)&src[e];
        int p0 = g_rowstart[d.x] + atomicAdd(&g_fill[d.x], 1);
        g_csr[p0] = sc.x;
        int p1 = g_rowstart[d.y] + atomicAdd(&g_fill[d.y], 1);
        g_csr[p1] = sc.y;
    }
}

// ---------------- layer-1 input aggregation (width 5; Â(XW) == (ÂX)W) ----------------
// xa[i] = dinv[i] * (dinv[i]*x[i] + sum_src dinv[src]*x[src])   (prescale fused)
__global__ void agg0_kernel(const float* __restrict__ x, float* __restrict__ xa) {
    int t = blockIdx.x * 256 + threadIdx.x;
    if (t >= NN * 5) return;
    int node = t / 5, f = t - node * 5;
    float dn = g_dinv[node];
    float acc = x[t] * dn;
    int s = g_rowstart[node], e = g_rowstart[node + 1];
    for (int j = s; j < e; j++) {
        int src = g_csr[j];
        acc += __ldg(&x[src * 5 + f]) * __ldg(&g_dinv[src]);
    }
    xa[t] = dn * acc;
}

// h1 = relu(xa @ W1 + b1), [N,5] -> [N,256]
__global__ void gemm1_kernel(const float* __restrict__ xa, const float* __restrict__ W1,
                             const float* __restrict__ b1, float* __restrict__ h1) {
    __shared__ float w[5 * 256];
    __shared__ float bs[256];
    for (int i = threadIdx.x; i < 1280; i += 256) w[i] = W1[i];
    bs[threadIdx.x] = b1[threadIdx.x];
    __syncthreads();
    int idx = blockIdx.x * 256 + threadIdx.x;   // node*64 + chunk
    if (idx >= NN * 64) return;
    int node = idx >> 6;
    int c = (idx & 63) * 4;
    float xv[5];
    #pragma unroll
    for (int k = 0; k < 5; k++) xv[k] = xa[node * 5 + k];
    float4 acc = make_float4(bs[c], bs[c + 1], bs[c + 2], bs[c + 3]);
    #pragma unroll
    for (int k = 0; k < 5; k++) {
        acc.x = fmaf(xv[k], w[k * 256 + c + 0], acc.x);
        acc.y = fmaf(xv[k], w[k * 256 + c + 1], acc.y);
        acc.z = fmaf(xv[k], w[k * 256 + c + 2], acc.z);
        acc.w = fmaf(xv[k], w[k * 256 + c + 3], acc.w);
    }
    acc.x = fmaxf(acc.x, 0.f); acc.y = fmaxf(acc.y, 0.f);
    acc.z = fmaxf(acc.z, 0.f); acc.w = fmaxf(acc.w, 0.f);
    ((float4*)h1)[idx] = acc;
}

// ---------------- TF32 tensor-core GEMM ----------------
// out[m,n] = rowscale[m] * sum_k affine(A[m,k]) * W[k,n]
template <int BM, int BN, int BK, int WM, int WN>
__global__ void gemm_tf32_kernel(const float* __restrict__ A, const float* __restrict__ W,
                                 float* __restrict__ out, int M, int K, int N,
                                 const float* __restrict__ affA, const float* __restrict__ affC,
                                 const float* __restrict__ rowscale) {
    constexpr int WARPS_M = BM / WM;
    constexpr int WARPS_N = BN / WN;
    constexpr int THREADS = WARPS_M * WARPS_N * 32;
    constexpr int MT = WM / 16;
    constexpr int NT = WN / 8;

    __shared__ unsigned As[BK][BM + 4];   // [k][m], tf32 bits
    __shared__ unsigned Bs[BK][BN + 4];   // [k][n], tf32 bits

    int tid = threadIdx.x;
    int lane = tid & 31;
    int wid = tid >> 5;
    int warpM = wid % WARPS_M;
    int warpN = wid / WARPS_M;
    int g = lane >> 2;
    int t = lane & 3;
    int rowBase = blockIdx.y * BM;
    int colBase = blockIdx.x * BN;

    float acc[MT][NT][4];
    #pragma unroll
    for (int i = 0; i < MT; i++)
        #pragma unroll
        for (int j = 0; j < NT; j++)
            #pragma unroll
            for (int q = 0; q < 4; q++) acc[i][j][q] = 0.f;

    for (int k0 = 0; k0 < K; k0 += BK) {
        #pragma unroll
        for (int it = tid; it < BM * BK / 4; it += THREADS) {
            int m = it / (BK / 4);
            int kq = (it % (BK / 4)) * 4;
            int gr = rowBase + m;
            float4 v = make_float4(0.f, 0.f, 0.f, 0.f);
            if (gr < M) {
                v = *(const float4*)&A[gr * K + k0 + kq];
                if (affA) {
                    v.x = fmaf(v.x, affA[k0 + kq + 0], affC[k0 + kq + 0]);
                    v.y = fmaf(v.y, affA[k0 + kq + 1], affC[k0 + kq + 1]);
                    v.z = fmaf(v.z, affA[k0 + kq + 2], affC[k0 + kq + 2]);
                    v.w = fmaf(v.w, affA[k0 + kq + 3], affC[k0 + kq + 3]);
                }
            }
            As[kq + 0][m] = cvt_tf32(v.x);
            As[kq + 1][m] = cvt_tf32(v.y);
            As[kq + 2][m] = cvt_tf32(v.z);
            As[kq + 3][m] = cvt_tf32(v.w);
        }
        #pragma unroll
        for (int it = tid; it < BK * BN / 4; it += THREADS) {
            int k = it / (BN / 4);
            int nq = (it % (BN / 4)) * 4;
            float4 v = *(const float4*)&W[(k0 + k) * N + colBase + nq];
            Bs[k][nq + 0] = cvt_tf32(v.x);
            Bs[k][nq + 1] = cvt_tf32(v.y);
            Bs[k][nq + 2] = cvt_tf32(v.z);
            Bs[k][nq + 3] = cvt_tf32(v.w);
        }
        __syncthreads();
        #pragma unroll
        for (int kk = 0; kk < BK; kk += 8) {
            unsigned a[MT][4], b[NT][2];
            #pragma unroll
            for (int mt = 0; mt < MT; mt++) {
                int mb = warpM * WM + mt * 16;
                a[mt][0] = As[kk + t][mb + g];
                a[mt][1] = As[kk + t][mb + g + 8];
                a[mt][2] = As[kk + t + 4][mb + g];
                a[mt][3] = As[kk + t + 4][mb + g + 8];
            }
            #pragma unroll
            for (int nt = 0; nt < NT; nt++) {
                int nb = warpN * WN + nt * 8;
                b[nt][0] = Bs[kk + t][nb + g];
                b[nt][1] = Bs[kk + t + 4][nb + g];
            }
            #pragma unroll
            for (int mt = 0; mt < MT; mt++)
                #pragma unroll
                for (int nt = 0; nt < NT; nt++)
                    mma_tf32(acc[mt][nt], a[mt], b[nt]);
        }
        __syncthreads();
    }

    #pragma unroll
    for (int mt = 0; mt < MT; mt++) {
        int r0 = rowBase + warpM * WM + mt * 16 + g;
        int r1 = r0 + 8;
        float rs0 = (r0 < M) ? (rowscale ? rowscale[r0] : 1.f) : 0.f;
        float rs1 = (r1 < M) ? (rowscale ? rowscale[r1] : 1.f) : 0.f;
        #pragma unroll
        for (int nt = 0; nt < NT; nt++) {
            int col = colBase + warpN * WN + nt * 8 + 2 * t;
            if (r0 < M) {
                float2 v = make_float2(acc[mt][nt][0] * rs0, acc[mt][nt][1] * rs0);
                *(float2*)&out[r0 * N + col] = v;
            }
            if (r1 < M) {
                float2 v = make_float2(acc[mt][nt][2] * rs1, acc[mt][nt][3] * rs1);
                *(float2*)&out[r1 * N + col] = v;
            }
        }
    }
}

// ---------------- CSR aggregation: out[i] = relu(dinv[i]*(u[i] + sum_src u[src]) + b) ----------------
template <int F>
__global__ void agg_kernel(const float* __restrict__ u, const float* __restrict__ bias,
                           float* __restrict__ out) {
    constexpr int CH = F / 4;          // float4 lanes per node
    constexpr int NPB = 256 / CH;      // nodes per block
    int node = blockIdx.x * NPB + threadIdx.x / CH;
    int lane = threadIdx.x % CH;
    if (node >= NN) return;
    const float4* u4 = (const float4*)u;
    float4 a0 = u4[node * CH + lane];   // self-loop term
    float4 a1 = make_float4(0.f, 0.f, 0.f, 0.f);
    float4 a2 = make_float4(0.f, 0.f, 0.f, 0.f);
    float4 a3 = make_float4(0.f, 0.f, 0.f, 0.f);
    int s = g_rowstart[node];
    int e = g_rowstart[node + 1];
    int j = s;
    for (; j + 4 <= e; j += 4) {
        int s0 = __ldg(&g_csr[j]);
        int s1 = __ldg(&g_csr[j + 1]);
        int s2 = __ldg(&g_csr[j + 2]);
        int s3 = __ldg(&g_csr[j + 3]);
        float4 v0 = __ldg(&u4[s0 * CH + lane]);
        float4 v1 = __ldg(&u4[s1 * CH + lane]);
        float4 v2 = __ldg(&u4[s2 * CH + lane]);
        float4 v3 = __ldg(&u4[s3 * CH + lane]);
        a0.x += v0.x; a0.y += v0.y; a0.z += v0.z; a0.w += v0.w;
        a1.x += v1.x; a1.y += v1.y; a1.z += v1.z; a1.w += v1.w;
        a2.x += v2.x; a2.y += v2.y; a2.z += v2.z; a2.w += v2.w;
        a3.x += v3.x; a3.y += v3.y; a3.z += v3.z; a3.w += v3.w;
    }
    for (; j < e; j++) {
        float4 v = __ldg(&u4[__ldg(&g_csr[j]) * CH + lane]);
        a0.x += v.x; a0.y += v.y; a0.z += v.z; a0.w += v.w;
    }
    a0.x += a1.x + a2.x + a3.x;
    a0.y += a1.y + a2.y + a3.y;
    a0.z += a1.z + a2.z + a3.z;
    a0.w += a1.w + a2.w + a3.w;
    float d = g_dinv[node];
    float4 b = ((const float4*)bias)[lane];
    float4 o;
    o.x = fmaxf(fmaf(d, a0.x, b.x), 0.f);
    o.y = fmaxf(fmaf(d, a0.y, b.y), 0.f);
    o.z = fmaxf(fmaf(d, a0.z, b.z), 0.f);
    o.w = fmaxf(fmaf(d, a0.w, b.w), 0.f);
    ((float4*)out)[node * CH + lane] = o;
}

// ---------------- batchnorm stats + fused finalize (last block) ----------------
__global__ void bn_stats(const float* __restrict__ h, int F,
                         float* __restrict__ sums, float* __restrict__ sqs,
                         const float* __restrict__ gamma, const float* __restrict__ beta,
                         float* __restrict__ a, float* __restrict__ c,
                         int* __restrict__ counter) {
    __shared__ float ss[256], sq[256];
    __shared__ bool isLast;
    int tid = threadIdx.x;
    long long idx = (long long)blockIdx.x * 256 + tid;
    long long total = (long long)NN * F;
    long long stride = (long long)gridDim.x * 256;   // multiple of F (F in {64,128})
    float s = 0.f, q = 0.f;
    for (; idx < total; idx += stride) {
        float v = h[idx];
        s += v; q += v * v;
    }
    ss[tid] = s; sq[tid] = q;
    __syncthreads();
    for (int off = 128; off >= F; off >>= 1) {
        if (tid < off) { ss[tid] += ss[tid + off]; sq[tid] += sq[tid + off]; }
        __syncthreads();
    }
    if (tid < F) {
        atomicAdd(&sums[tid], ss[tid]);
        atomicAdd(&sqs[tid], sq[tid]);
    }
    __threadfence();
    __syncthreads();
    if (tid == 0) isLast = (atomicAdd(counter, 1) == (int)gridDim.x - 1);
    __syncthreads();
    if (isLast && tid < F) {
        float mean = sums[tid] * (1.0f / NN);
        float var = sqs[tid] * (1.0f / NN) - mean * mean;
        float aa = gamma[tid] * rsqrtf(var + EPSV);
        a[tid] = aa;
        c[tid] = beta[tid] - mean * aa;
    }
}

// ---------------- global mean pool + fused FC head (last block) ----------------
__device__ __forceinline__ int lower_bound_i(const int* arr, int n, int val) {
    int lo = 0, hi = n;
    while (lo < hi) {
        int mid = (lo + hi) >> 1;
        if (arr[mid] < val) lo = mid + 1; else hi = mid;
    }
    return lo;
}

// grid (NG, 4): 4 partial blocks per graph; last finished block runs bn2+FC.
__global__ void pool_kernel(const int* __restrict__ batch, const float* __restrict__ h,
                            const float* __restrict__ Wfc, const float* __restrict__ bfc,
                            float* __restrict__ out) {
    int g = blockIdx.x, part = blockIdx.y;
    int start = lower_bound_i(batch, NN, g);
    int end   = lower_bound_i(batch, NN, g + 1);
    int tid = threadIdx.x;
    int f = tid & 63, r0 = tid >> 6;   // r0 in 0..3
    float s = 0.f;
    for (int r = start + part * 4 + r0; r < end; r += 16) s += h[r * 64 + f];
    __shared__ float sm[256];
    __shared__ bool isLast;
    sm[tid] = s;
    __syncthreads();
    if (tid < 128) sm[tid] += sm[tid + 128];
    __syncthreads();
    if (tid < 64) atomicAdd(&g_pool[g * 64 + tid], sm[tid] + sm[tid + 64]);
    if (part == 0 && tid == 0) g_cnt[g] = end - start;
    __threadfence();
    __syncthreads();
    if (tid == 0) isLast = (atomicAdd(&g_ctr[2], 1) == NG * 4 - 1);
    __syncthreads();
    if (isLast) {
        for (int t2 = tid; t2 < NG * 6; t2 += 256) {
            int gg = t2 / 6, cl = t2 % 6;
            float inv = 1.f / fmaxf((float)g_cnt[gg], 1.f);
            float acc = bfc[cl];
            #pragma unroll
            for (int j = 0; j < 64; j++) {
                float p = fmaf(g_a[128 + j], g_pool[gg * 64 + j] * inv, g_c[128 + j]);
                acc = fmaf(p, Wfc[j * 6 + cl], acc);
            }
            out[gg * 6 + cl] = acc;
        }
    }
}

// ---------------- host orchestration ----------------
extern "C" void kernel_launch(void* const* d_in, const int* in_sizes, int n_in,
                              void* d_out, int out_size) {
    const float* x      = (const float*)d_in[0];
    const int*   edge   = (const int*)d_in[1];   // int32 (JAX x64 disabled)
    const int*   batch  = (const int*)d_in[2];   // int32
    const float* W1     = (const float*)d_in[3];
    const float* b1     = (const float*)d_in[4];
    const float* W2     = (const float*)d_in[5];
    const float* b2     = (const float*)d_in[6];
    const float* gamma1 = (const float*)d_in[7];
    const float* beta1  = (const float*)d_in[8];
    const float* W3     = (const float*)d_in[9];
    const float* b3     = (const float*)d_in[10];
    const float* gamma2 = (const float*)d_in[11];
    const float* beta2  = (const float*)d_in[12];
    const float* Wfc    = (const float*)d_in[13];
    const float* bfc    = (const float*)d_in[14];
    float* out = (float*)d_out;

    const int* srcp = edge;
    const int* dstp = edge + NE;

    float *bufA, *bufB, *dinv, *bnsum, *bnsq, *aArr, *cArr;
    int* ctr;
    cudaGetSymbolAddress((void**)&bufA,  g_bufA);
    cudaGetSymbolAddress((void**)&bufB,  g_bufB);
    cudaGetSymbolAddress((void**)&dinv,  g_dinv);
    cudaGetSymbolAddress((void**)&bnsum, g_bnsum);
    cudaGetSymbolAddress((void**)&bnsq,  g_bnsq);
    cudaGetSymbolAddress((void**)&aArr,  g_a);
    cudaGetSymbolAddress((void**)&cArr,  g_c);
    cudaGetSymbolAddress((void**)&ctr,   g_ctr);

    // graph preprocessing (once per launch, reused by all 3 layers)
    zero_kernel<<<(NN + 255) / 256, 256>>>();
    count_kernel<<<(NE / 2 + 255) / 256, 256>>>(dstp);
    scan_kernel<<<1, 1024>>>();
    prep_kernel<<<(NN + 255) / 256, 256>>>();
    fill_kernel<<<(NE / 2 + 255) / 256, 256>>>(srcp, dstp);

    // layer 1 (reassociated): xa = Â x (width 5), then h1 = relu(xa @ W1 + b1)
    agg0_kernel<<<(NN * 5 + 255) / 256, 256>>>(x, bufA);              // xa -> bufA
    gemm1_kernel<<<(NN * 64 + 255) / 256, 256>>>(bufA, W1, b1, bufB); // h1 -> bufB

    // layer 2 (TF32): u2 = dinv * (h1 @ W2) -> bufA; agg -> h2 -> bufB; bn1 stats+finalize
    gemm_tf32_kernel<128, 128, 32, 32, 64><<<dim3(1, (NN + 127) / 128), 256>>>(
        bufB, W2, bufA, NN, 256, 128, nullptr, nullptr, dinv);
    agg_kernel<128><<<(NN + 7) / 8, 256>>>(bufA, b2, bufB);
    bn_stats<<<296, 256>>>(bufB, 128, bnsum, bnsq, gamma1, beta1, aArr, cArr, ctr + 0);

    // layer 3 (TF32): bn1 folded into A-load; u3 = dinv * (bn1(h2) @ W3) -> bufA; agg -> h3 -> bufB
    gemm_tf32_kernel<128, 64, 32, 32, 64><<<dim3(1, (NN + 127) / 128), 128>>>(
        bufB, W3, bufA, NN, 128, 64, aArr, cArr, dinv);
    agg_kernel<64><<<(NN + 15) / 16, 256>>>(bufA, b3, bufB);
    bn_stats<<<296, 256>>>(bufB, 64, bnsum + 128, bnsq + 128, gamma2, beta2,
                           aArr + 128, cArr + 128, ctr + 1);

    // pool + bn2(folded) + FC head (fused)
    pool_kernel<<<dim3(NG, 4), 256>>>(batch, bufB, Wfc, bfc, out);
}